// round 3
// baseline (speedup 1.0000x reference)
#include <cuda_runtime.h>

typedef unsigned long long u64t;

// ---- packed f32x2 helpers (sm_103a) ----
__device__ __forceinline__ u64t pack2(float x, float y){
    u64t r; asm("mov.b64 %0,{%1,%2};" : "=l"(r) : "f"(x), "f"(y)); return r;
}
__device__ __forceinline__ float2 unpack2(u64t a){
    float2 r; asm("mov.b64 {%0,%1},%2;" : "=f"(r.x), "=f"(r.y) : "l"(a)); return r;
}
__device__ __forceinline__ u64t fma2_(u64t a, u64t b, u64t c){
    u64t d; asm("fma.rn.f32x2 %0,%1,%2,%3;" : "=l"(d) : "l"(a), "l"(b), "l"(c)); return d;
}
__device__ __forceinline__ u64t mul2_(u64t a, u64t b){
    u64t d; asm("mul.rn.f32x2 %0,%1,%2;" : "=l"(d) : "l"(a), "l"(b)); return d;
}
__device__ __forceinline__ u64t add2_(u64t a, u64t b){
    u64t d; asm("add.rn.f32x2 %0,%1,%2;" : "=l"(d) : "l"(a), "l"(b)); return d;
}

#define NB   32      // batches
#define NI   4096    // input capsules
#define NO   32      // output capsules
#define CI   32      // i per block
#define NBLK 128     // NI / CI
#define WPB  8       // warps per block
#define IPW  4       // i per warp

// scratch (static device globals — no allocations)
__device__ __align__(16) float g_part[NBLK * NB * NO * 16];  // 8 MB partials
__device__ __align__(16) float g_v[NB * NO * 16];            // v used for logits this pass
__device__ __align__(16) float g_vsum[NB * NO * 16];         // v0 (running sum)

// ---------------------------------------------------------------------------
// Pass kernel: block = 32-i chunk; lane = o; warp = 4 i's; loop over 32 batches.
// Computes votes on the fly, (optionally) softmax-coupled weights, accumulates
// s per (b,o) in registers, block-reduces to g_part[blk][b][o][16].
// ---------------------------------------------------------------------------
template<bool FIRST>
__global__ __launch_bounds__(256) void pass_kernel(const float* __restrict__ poses,
                                                   const float* __restrict__ w)
{
    __shared__ u64t Ps[2][CI * 16];       // poses chunk, scalars duplicated to f32x2
    __shared__ u64t red[WPB][NO][9];      // per-warp s partials (padded)

    const int tid  = threadIdx.x;
    const int lane = tid & 31;
    const int warp = tid >> 5;
    const int blk  = blockIdx.x;
    const int o    = lane;

    // W for my 4 i's, kept in registers for all 32 batches.
    // layout w[o][i][y][z]; pairs over z: W[j][y*2+zp]
    u64t W[IPW][8];
    {
        const float4* wp = (const float4*)(w + ((size_t)o * NI + (size_t)blk * CI + warp * IPW) * 16);
        #pragma unroll
        for (int j = 0; j < IPW; j++) {
            #pragma unroll
            for (int y = 0; y < 4; y++) {
                float4 t4 = wp[j * 4 + y];
                W[j][2 * y]     = pack2(t4.x, t4.y);
                W[j][2 * y + 1] = pack2(t4.z, t4.w);
            }
        }
    }

    // stage poses for batch b into shared (each scalar duplicated into both halves)
    auto stageP = [&](int b, int buf) {
        const float2* src = (const float2*)(poses + ((size_t)b * NI + (size_t)blk * CI) * 16);
        float2 pv = src[tid];                 // 256 threads x float2 = 512 floats
        Ps[buf][2 * tid]     = pack2(pv.x, pv.x);
        Ps[buf][2 * tid + 1] = pack2(pv.y, pv.y);
    };

    stageP(0, 0);
    __syncthreads();

    for (int b = 0; b < NB; b++) {
        u64t vreg[8];
        if (!FIRST) {
            const u64t* gv = (const u64t*)(g_v + ((size_t)b * NO + o) * 16);
            #pragma unroll
            for (int q = 0; q < 8; q++) vreg[q] = gv[q];
        }

        u64t sacc[8];
        #pragma unroll
        for (int q = 0; q < 8; q++) sacc[q] = 0ull;   // (0.0f, 0.0f)

        const u64t* Pb = Ps[b & 1];

        #pragma unroll
        for (int j = 0; j < IPW; j++) {
            const u64t* Pi = Pb + (warp * IPW + j) * 16;
            // votes V[x][z] = sum_y P[x][y] * W[y][z]  (packed over z pairs)
            u64t V[8];
            #pragma unroll
            for (int x = 0; x < 4; x++) {
                u64t p0 = Pi[x * 4 + 0];
                V[2 * x]     = mul2_(p0, W[j][0]);
                V[2 * x + 1] = mul2_(p0, W[j][1]);
                #pragma unroll
                for (int y = 1; y < 4; y++) {
                    u64t p = Pi[x * 4 + y];
                    V[2 * x]     = fma2_(p, W[j][2 * y],     V[2 * x]);
                    V[2 * x + 1] = fma2_(p, W[j][2 * y + 1], V[2 * x + 1]);
                }
            }

            if (FIRST) {
                // c = 1/32 uniform; apply scale later in reduce kernel
                #pragma unroll
                for (int q = 0; q < 8; q++) sacc[q] = add2_(sacc[q], V[q]);
            } else {
                // logit = <V, v>   (per-lane scalar)
                u64t d = mul2_(V[0], vreg[0]);
                #pragma unroll
                for (int q = 1; q < 8; q++) d = fma2_(V[q], vreg[q], d);
                float2 dd = unpack2(d);
                float e = __expf(dd.x + dd.y);      // logits bounded, no max-shift needed
                float den = e;
                #pragma unroll
                for (int sh = 16; sh > 0; sh >>= 1)
                    den += __shfl_xor_sync(0xffffffffu, den, sh);
                float c = __fdividef(e, den);
                u64t cp = pack2(c, c);
                #pragma unroll
                for (int q = 0; q < 8; q++) sacc[q] = fma2_(cp, V[q], sacc[q]);
            }
        }

        // per-warp partials to shared
        #pragma unroll
        for (int q = 0; q < 8; q++) red[warp][o][q] = sacc[q];
        // prefetch next batch's poses into the other buffer
        if (b + 1 < NB) stageP(b + 1, (b + 1) & 1);
        __syncthreads();

        // cross-warp reduce: 256 threads, thread -> (oo = tid>>3, q = tid&7)
        {
            int oo = tid >> 3, q = tid & 7;
            u64t a = red[0][oo][q];
            #pragma unroll
            for (int ww = 1; ww < WPB; ww++) a = add2_(a, red[ww][oo][q]);
            float2 av = unpack2(a);
            float2* gp = (float2*)(g_part + ((size_t)blk * NB + b) * NO * 16);
            gp[oo * 8 + q] = av;
        }
        __syncthreads();
    }
}

// ---------------------------------------------------------------------------
// Reduce partials over 128 blocks + squash. 16384 threads; 16 lanes = one (b,o).
// PASS 0: v0 -> g_v, g_vsum.  PASS 1: g_v = v0 + v1.  PASS 2: write output.
// ---------------------------------------------------------------------------
template<int PASS>
__global__ __launch_bounds__(256) void rs_kernel(float* __restrict__ out)
{
    int t = blockIdx.x * 256 + threadIdx.x;     // 0..16383 = b*512 + o*16 + k
    float s = 0.f;
    const float* p = g_part + t;
    #pragma unroll 8
    for (int q = 0; q < NBLK; q++) s += p[(size_t)q * (NB * NO * 16)];
    if (PASS == 0) s *= (1.0f / 32.0f);         // uniform c on iter 0

    float n2 = s * s;
    #pragma unroll
    for (int sh = 1; sh < 16; sh <<= 1)
        n2 += __shfl_xor_sync(0xffffffffu, n2, sh);   // sum over the 16 pose elems

    float n = sqrtf(n2 + 1e-12f);
    float f = n2 / ((1.0f + n2) * n);
    float v = s * f;

    if (PASS == 0)      { g_v[t] = v; g_vsum[t] = v; }
    else if (PASS == 1) { g_v[t] = g_vsum[t] + v; }
    else {
        out[t] = v;                                     // capsule_poses [B,O,4,4]
        if ((t & 15) == 0)
            out[NB * NO * 16 + (t >> 4)] = sqrtf(n2 * f * f + 1e-12f);  // activations
    }
}

extern "C" void kernel_launch(void* const* d_in, const int* in_sizes, int n_in,
                              void* d_out, int out_size)
{
    const float* poses = (const float*)d_in[0];
    // d_in[1] = input_activations — unused by the reference math
    const float* w     = (const float*)d_in[2];
    float* out = (float*)d_out;

    pass_kernel<true ><<<NBLK, 256>>>(poses, w);
    rs_kernel<0><<<64, 256>>>(nullptr);
    pass_kernel<false><<<NBLK, 256>>>(poses, w);
    rs_kernel<1><<<64, 256>>>(nullptr);
    pass_kernel<false><<<NBLK, 256>>>(poses, w);
    rs_kernel<2><<<64, 256>>>(out);
}